// round 6
// baseline (speedup 1.0000x reference)
#include <cuda_runtime.h>
#include <math.h>

// Problem constants
#define BB 64          // batch
#define TT 512         // time steps
#define HH 1024        // hidden
#define EE 300         // embedding dim

#define GRID_SCAN 128  // persistent blocks (<=148 SMs, 1 block/SM via SMEM)
#define TPB_SCAN  128
#define HB 8           // h-columns owned per scan block (128*8 = 1024)

// ---------------- device scratch (no allocations allowed) ----------------
__device__ __align__(256) float    g_pre0[(size_t)TT * HH * BB]; // [t][h][b], 128 MB
__device__ __align__(256) float    g_h1[2][HH * BB];             // ping-pong [k][b]
__device__ __align__(256) float    g_h2[2][HH * BB];
__device__ unsigned                g_bar;

// ---------------- helpers ----------------
__device__ __forceinline__ void cpasync16(float* smem, const float* gmem) {
    unsigned s = (unsigned)__cvta_generic_to_shared(smem);
    // .cg => L2-only. REQUIRED: state buffers are rewritten by other SMs
    // between steps; L1 would serve stale lines.
    asm volatile("cp.async.cg.shared.global [%0], [%1], 16;" :: "r"(s), "l"(gmem));
}
#define CP_COMMIT() asm volatile("cp.async.commit_group;" ::: "memory")
#define CP_WAIT1()  asm volatile("cp.async.wait_group 1;" ::: "memory")

// Monotone grid barrier: counter zeroed by k_init each launch; blocks wait
// until count >= n*GRID_SCAN. All blocks are co-resident (1 block/SM, 128<=148).
__device__ __forceinline__ void gsync(unsigned n) {
    __threadfence();            // make this thread's STGs visible at L2
    __syncthreads();
    if (threadIdx.x == 0) {
        atomicAdd(&g_bar, 1u);
        const unsigned tgt = n * GRID_SCAN;
        while (*((volatile unsigned*)&g_bar) < tgt) { }
    }
    __syncthreads();
}

// ======================================================================
// Kernel 1: pre0[t][h][b] = sum_e emb[x[b][t]][e]*W_ih0[h][e] + b_ih0[h] + b_hh0[h]
// Block = 256 threads computes a 64(b at fixed t) x 64(h) tile, K=300 in SMEM.
// ======================================================================
__global__ void k_pre0(const int* __restrict__ x, const float* __restrict__ emb,
                       const float* __restrict__ Wih0,
                       const float* __restrict__ bih0, const float* __restrict__ bhh0) {
    extern __shared__ float sm[];
    float* As = sm;             // [300][65]  As[c*65 + b]   (pad 65 => conflict-free stage)
    float* Ws = sm + EE * 65;   // [300][65]  Ws[c*65 + hl]
    __shared__ int toks[64];

    const int tid   = threadIdx.x;
    const int t     = blockIdx.y;
    const int hbase = blockIdx.x * 64;

    if (tid < 64) toks[tid] = x[tid * TT + t];   // x is [B][T], row b = tid
    __syncthreads();

    for (int idx = tid; idx < 64 * EE; idx += 256) {
        int r = idx / EE, c = idx - r * EE;
        As[c * 65 + r] = emb[(size_t)toks[r] * EE + c];
        Ws[c * 65 + r] = Wih0[(size_t)(hbase + r) * EE + c];
    }
    __syncthreads();

    const int tx = tid & 15;    // b-quad
    const int ty = tid >> 4;    // h-quad
    float acc[4][4];
#pragma unroll
    for (int j = 0; j < 4; j++)
#pragma unroll
        for (int i = 0; i < 4; i++) acc[j][i] = 0.f;

#pragma unroll 4
    for (int c = 0; c < EE; c++) {
        const float* ap = As + c * 65 + tx * 4;
        const float* wp = Ws + c * 65 + ty * 4;
        float a0 = ap[0], a1 = ap[1], a2 = ap[2], a3 = ap[3];
        float w0 = wp[0], w1 = wp[1], w2 = wp[2], w3 = wp[3];
        acc[0][0] += w0 * a0; acc[0][1] += w0 * a1; acc[0][2] += w0 * a2; acc[0][3] += w0 * a3;
        acc[1][0] += w1 * a0; acc[1][1] += w1 * a1; acc[1][2] += w1 * a2; acc[1][3] += w1 * a3;
        acc[2][0] += w2 * a0; acc[2][1] += w2 * a1; acc[2][2] += w2 * a2; acc[2][3] += w2 * a3;
        acc[3][0] += w3 * a0; acc[3][1] += w3 * a1; acc[3][2] += w3 * a2; acc[3][3] += w3 * a3;
    }

#pragma unroll
    for (int j = 0; j < 4; j++) {
        int h = hbase + ty * 4 + j;
        float bs = bih0[h] + bhh0[h];
        float4 v = make_float4(acc[j][0] + bs, acc[j][1] + bs, acc[j][2] + bs, acc[j][3] + bs);
        *(float4*)(&g_pre0[((size_t)t * HH + h) * BB + tx * 4]) = v;
    }
}

// ======================================================================
// Kernel 2: persistent 512-step scan of both RNN layers.
// Block g owns h-columns [g*8, g*8+8). Weights resident in SMEM for all steps.
// Thread (hl = tid>>4, q = tid&15) accumulates 4 b's (b = 4q..4q+3) for one h.
// ======================================================================
__global__ void __launch_bounds__(TPB_SCAN, 1)
k_scan(const float* __restrict__ Whh0, const float* __restrict__ Wih1,
       const float* __restrict__ Whh1,
       const float* __restrict__ bih1, const float* __restrict__ bhh1) {
    extern __shared__ float sm[];
    float* w0s   = sm;                 // [8][1024] rows of W_hh0 for owned h
    float* wi1s  = w0s  + HB * HH;     // [8][1024]
    float* wh1s  = wi1s + HB * HH;     // [8][1024]
    float* tA0   = wh1s + HB * HH;     // [64][64] state tile ping
    float* tA1   = tA0 + 4096;         //          pong
    float* tB0   = tA1 + 4096;
    float* tB1   = tB0 + 4096;
    float* bias2 = tB1 + 4096;         // [8] = b_ih1 + b_hh1 for owned h

    const int g   = blockIdx.x;
    const int tid = threadIdx.x;
    const int q4  = (tid & 15) * 4;
    const int hl  = tid >> 4;
    const int h   = g * HB + hl;

    // Load this block's weight slices once (straight row copies, coalesced).
    for (int idx = tid; idx < HB * HH / 4; idx += TPB_SCAN) {
        int j  = idx >> 8;               // /256 : local h row
        int k4 = idx & 255;
        ((float4*)w0s)[idx]  = ((const float4*)(Whh0 + (size_t)(g * HB + j) * HH))[k4];
        ((float4*)wi1s)[idx] = ((const float4*)(Wih1 + (size_t)(g * HB + j) * HH))[k4];
        ((float4*)wh1s)[idx] = ((const float4*)(Whh1 + (size_t)(g * HB + j) * HH))[k4];
    }
    if (tid < HB) bias2[tid] = bih1[g * HB + tid] + bhh1[g * HB + tid];
    __syncthreads();

    unsigned syncno = 0;

    for (int t = 0; t < TT; t++) {
        const int cur = t & 1, prv = cur ^ 1;

        // ---------------- phase 1: h1_t = tanh(pre0_t + h1_{t-1} @ W_hh0^T) --
        {
            float4 acc = *(const float4*)(&g_pre0[((size_t)t * HH + h) * BB + q4]);
            const float* st = g_h1[prv];

#pragma unroll
            for (int j = 0; j < 8; j++) {            // prefetch chunk 0
                int i2 = tid + j * TPB_SCAN;
                cpasync16(tA0 + i2 * 4, st + i2 * 4);
            }
            CP_COMMIT();

            for (int c = 0; c < 16; c++) {
                if (c + 1 < 16) {
                    const float* s2 = st + (c + 1) * 4096;
                    float* dst = ((c + 1) & 1) ? tA1 : tA0;
#pragma unroll
                    for (int j = 0; j < 8; j++) {
                        int i2 = tid + j * TPB_SCAN;
                        cpasync16(dst + i2 * 4, s2 + i2 * 4);
                    }
                }
                CP_COMMIT();
                CP_WAIT1();
                __syncthreads();

                const float* wrow = w0s + hl * HH + c * 64;
                const float* tile = (c & 1) ? tA1 : tA0;
#pragma unroll 4
                for (int kk = 0; kk < 64; kk += 4) {
                    float4 w4 = *(const float4*)(wrow + kk);
                    float4 a;
                    a = *(const float4*)(tile + (kk + 0) * 64 + q4);
                    acc.x += w4.x * a.x; acc.y += w4.x * a.y; acc.z += w4.x * a.z; acc.w += w4.x * a.w;
                    a = *(const float4*)(tile + (kk + 1) * 64 + q4);
                    acc.x += w4.y * a.x; acc.y += w4.y * a.y; acc.z += w4.y * a.z; acc.w += w4.y * a.w;
                    a = *(const float4*)(tile + (kk + 2) * 64 + q4);
                    acc.x += w4.z * a.x; acc.y += w4.z * a.y; acc.z += w4.z * a.z; acc.w += w4.z * a.w;
                    a = *(const float4*)(tile + (kk + 3) * 64 + q4);
                    acc.x += w4.w * a.x; acc.y += w4.w * a.y; acc.z += w4.w * a.z; acc.w += w4.w * a.w;
                }
                __syncthreads();
            }
            float4 r = make_float4(tanhf(acc.x), tanhf(acc.y), tanhf(acc.z), tanhf(acc.w));
            *(float4*)(&g_h1[cur][h * BB + q4]) = r;
        }
        gsync(++syncno);

        // ---- phase 2: h2_t = tanh(h1_t @ W_ih1^T + h2_{t-1} @ W_hh1^T + b) --
        {
            const float bb = bias2[hl];
            float4 acc = make_float4(bb, bb, bb, bb);
            const float* sA = g_h1[cur];
            const float* sB = g_h2[prv];

#pragma unroll
            for (int j = 0; j < 8; j++) {
                int i2 = tid + j * TPB_SCAN;
                cpasync16(tA0 + i2 * 4, sA + i2 * 4);
                cpasync16(tB0 + i2 * 4, sB + i2 * 4);
            }
            CP_COMMIT();

            for (int c = 0; c < 16; c++) {
                if (c + 1 < 16) {
                    const float* s2a = sA + (c + 1) * 4096;
                    const float* s2b = sB + (c + 1) * 4096;
                    float* da = ((c + 1) & 1) ? tA1 : tA0;
                    float* db = ((c + 1) & 1) ? tB1 : tB0;
#pragma unroll
                    for (int j = 0; j < 8; j++) {
                        int i2 = tid + j * TPB_SCAN;
                        cpasync16(da + i2 * 4, s2a + i2 * 4);
                        cpasync16(db + i2 * 4, s2b + i2 * 4);
                    }
                }
                CP_COMMIT();
                CP_WAIT1();
                __syncthreads();

                const float* wrA = wi1s + hl * HH + c * 64;
                const float* wrB = wh1s + hl * HH + c * 64;
                const float* ta  = (c & 1) ? tA1 : tA0;
                const float* tb  = (c & 1) ? tB1 : tB0;
#pragma unroll 4
                for (int kk = 0; kk < 64; kk += 4) {
                    float4 wa = *(const float4*)(wrA + kk);
                    float4 wb = *(const float4*)(wrB + kk);
                    float4 a, b;
                    a = *(const float4*)(ta + (kk + 0) * 64 + q4);
                    b = *(const float4*)(tb + (kk + 0) * 64 + q4);
                    acc.x += wa.x * a.x + wb.x * b.x; acc.y += wa.x * a.y + wb.x * b.y;
                    acc.z += wa.x * a.z + wb.x * b.z; acc.w += wa.x * a.w + wb.x * b.w;
                    a = *(const float4*)(ta + (kk + 1) * 64 + q4);
                    b = *(const float4*)(tb + (kk + 1) * 64 + q4);
                    acc.x += wa.y * a.x + wb.y * b.x; acc.y += wa.y * a.y + wb.y * b.y;
                    acc.z += wa.y * a.z + wb.y * b.z; acc.w += wa.y * a.w + wb.y * b.w;
                    a = *(const float4*)(ta + (kk + 2) * 64 + q4);
                    b = *(const float4*)(tb + (kk + 2) * 64 + q4);
                    acc.x += wa.z * a.x + wb.z * b.x; acc.y += wa.z * a.y + wb.z * b.y;
                    acc.z += wa.z * a.z + wb.z * b.z; acc.w += wa.z * a.w + wb.z * b.w;
                    a = *(const float4*)(ta + (kk + 3) * 64 + q4);
                    b = *(const float4*)(tb + (kk + 3) * 64 + q4);
                    acc.x += wa.w * a.x + wb.w * b.x; acc.y += wa.w * a.y + wb.w * b.y;
                    acc.z += wa.w * a.z + wb.w * b.z; acc.w += wa.w * a.w + wb.w * b.w;
                }
                __syncthreads();
            }
            float4 r = make_float4(tanhf(acc.x), tanhf(acc.y), tanhf(acc.z), tanhf(acc.w));
            *(float4*)(&g_h2[cur][h * BB + q4]) = r;
        }
        gsync(++syncno);
    }
}

// ======================================================================
// Kernel 3: out[b] = sigmoid(h2_last[:,b] . W_fc + b_fc).  Last step t=511 -> buf 1.
// ======================================================================
__global__ void k_fc(const float* __restrict__ Wfc, const float* __restrict__ bfc,
                     float* __restrict__ out) {
    __shared__ float red[256];
    const int tid = threadIdx.x;
    const int b = tid & 63, part = tid >> 6;
    float s = 0.f;
    for (int hh = part * 256; hh < part * 256 + 256; hh++)
        s += g_h2[1][hh * BB + b] * Wfc[hh];
    red[tid] = s;
    __syncthreads();
    if (tid < 64) {
        float v = red[tid] + red[tid + 64] + red[tid + 128] + red[tid + 192] + bfc[0];
        out[b] = 1.f / (1.f + expf(-v));
    }
}

// ======================================================================
// Kernel 0: per-launch reset (states for t=0 read buffer 1; barrier counter).
// ======================================================================
__global__ void k_init() {
    int i = blockIdx.x * blockDim.x + threadIdx.x;
    if (i == 0) g_bar = 0u;
    if (i < HH * BB) { g_h1[1][i] = 0.f; g_h2[1][i] = 0.f; }
}

// ======================================================================
extern "C" void kernel_launch(void* const* d_in, const int* in_sizes, int n_in,
                              void* d_out, int out_size) {
    const int*   x    = (const int*)  d_in[0];
    const float* emb  = (const float*)d_in[1];
    const float* Wih0 = (const float*)d_in[2];
    const float* Whh0 = (const float*)d_in[3];
    const float* bih0 = (const float*)d_in[4];
    const float* bhh0 = (const float*)d_in[5];
    const float* Wih1 = (const float*)d_in[6];
    const float* Whh1 = (const float*)d_in[7];
    const float* bih1 = (const float*)d_in[8];
    const float* bhh1 = (const float*)d_in[9];
    const float* Wfc  = (const float*)d_in[10];
    const float* bfc  = (const float*)d_in[11];
    float* out = (float*)d_out;

    const int pre0_smem = 2 * EE * 65 * (int)sizeof(float);                  // 156,000 B
    const int scan_smem = (3 * HB * HH + 4 * 4096 + 16) * (int)sizeof(float); // ~163.9 KB
    cudaFuncSetAttribute(k_pre0, cudaFuncAttributeMaxDynamicSharedMemorySize, pre0_smem);
    cudaFuncSetAttribute(k_scan, cudaFuncAttributeMaxDynamicSharedMemorySize, scan_smem);

    k_init<<<(HH * BB + 255) / 256, 256>>>();
    k_pre0<<<dim3(HH / 64, TT), 256, pre0_smem>>>(x, emb, Wih0, bih0, bhh0);
    k_scan<<<GRID_SCAN, TPB_SCAN, scan_smem>>>(Whh0, Wih1, Whh1, bih1, bhh1);
    k_fc<<<1, 256>>>(Wfc, bfc, out);
}

// round 7
// speedup vs baseline: 2.0657x; 2.0657x over previous
#include <cuda_runtime.h>
#include <math.h>

// Problem constants
#define BB 64          // batch
#define TT 512         // time steps
#define HH 1024        // hidden
#define EE 300         // embedding dim

#define GRID_SCAN 128  // persistent blocks, 1 block/SM via SMEM => all co-resident
#define TPB_SCAN  256
#define HB 8           // h-rows owned per scan block (128*8 = 1024)

typedef unsigned long long ull;

// ---------------- device scratch (no allocations allowed) ----------------
__device__ __align__(256) float g_pre0[(size_t)TT * HH * BB]; // [t][h][b], 128 MB
__device__ __align__(256) float g_h1[2][HH * BB];             // ping-pong [h][b]
__device__ __align__(256) float g_h2[2][HH * BB];
__device__ unsigned             g_bar;

// ---------------- packed f32x2 helpers ----------------
#define FFMA2(d, a, b) asm("fma.rn.f32x2 %0, %1, %2, %0;" : "+l"(d) : "l"(a), "l"(b))
#define FADD2(d, a)    asm("add.rn.f32x2 %0, %0, %1;"     : "+l"(d) : "l"(a))

union F4U { float4 f; ull u[2]; };

// Monotone grid barrier: counter zeroed by k_init each launch.
__device__ __forceinline__ void gsync(unsigned n) {
    __threadfence();
    __syncthreads();
    if (threadIdx.x == 0) {
        atomicAdd(&g_bar, 1u);
        const unsigned tgt = n * GRID_SCAN;
        while (*((volatile unsigned*)&g_bar) < tgt) { }
    }
    __syncthreads();
}

// ======================================================================
// Kernel 1: pre0[t][h][b] = sum_e emb[x[b][t]][e]*W_ih0[h][e] + b_ih0[h] + b_hh0[h]
// ======================================================================
__global__ void k_pre0(const int* __restrict__ x, const float* __restrict__ emb,
                       const float* __restrict__ Wih0,
                       const float* __restrict__ bih0, const float* __restrict__ bhh0) {
    extern __shared__ float sm[];
    float* As = sm;             // [300][65]
    float* Ws = sm + EE * 65;   // [300][65]
    __shared__ int toks[64];

    const int tid   = threadIdx.x;
    const int t     = blockIdx.y;
    const int hbase = blockIdx.x * 64;

    if (tid < 64) toks[tid] = x[tid * TT + t];
    __syncthreads();

    for (int idx = tid; idx < 64 * EE; idx += 256) {
        int r = idx / EE, c = idx - r * EE;
        As[c * 65 + r] = emb[(size_t)toks[r] * EE + c];
        Ws[c * 65 + r] = Wih0[(size_t)(hbase + r) * EE + c];
    }
    __syncthreads();

    const int tx = tid & 15;    // b-quad
    const int ty = tid >> 4;    // h-quad
    float acc[4][4];
#pragma unroll
    for (int j = 0; j < 4; j++)
#pragma unroll
        for (int i = 0; i < 4; i++) acc[j][i] = 0.f;

#pragma unroll 4
    for (int c = 0; c < EE; c++) {
        const float* ap = As + c * 65 + tx * 4;
        const float* wp = Ws + c * 65 + ty * 4;
        float a0 = ap[0], a1 = ap[1], a2 = ap[2], a3 = ap[3];
        float w0 = wp[0], w1 = wp[1], w2 = wp[2], w3 = wp[3];
        acc[0][0] += w0 * a0; acc[0][1] += w0 * a1; acc[0][2] += w0 * a2; acc[0][3] += w0 * a3;
        acc[1][0] += w1 * a0; acc[1][1] += w1 * a1; acc[1][2] += w1 * a2; acc[1][3] += w1 * a3;
        acc[2][0] += w2 * a0; acc[2][1] += w2 * a1; acc[2][2] += w2 * a2; acc[2][3] += w2 * a3;
        acc[3][0] += w3 * a0; acc[3][1] += w3 * a1; acc[3][2] += w3 * a2; acc[3][3] += w3 * a3;
    }

#pragma unroll
    for (int j = 0; j < 4; j++) {
        int h = hbase + ty * 4 + j;
        float bs = bih0[h] + bhh0[h];
        float4 v = make_float4(acc[j][0] + bs, acc[j][1] + bs, acc[j][2] + bs, acc[j][3] + bs);
        *(float4*)(&g_pre0[((size_t)t * HH + h) * BB + tx * 4]) = v;
    }
}

// ======================================================================
// Kernel 2: persistent scan. Iter t computes h1[t] AND h2[t-1] (lagged),
// sharing the h1[t-1] operand; ONE grid barrier per iter.
//
// Block g owns h rows [g*8, g*8+8). Weights live in SMEM pre-duplicated
// as (w,w) float2 pairs, transposed to [k][h] so FFMA2 needs no packing.
// Thread: warp w handles k in [w*128,(w+1)*128); lane = bq(16) x klane(2);
// each thread: all 8 h  x  4 b  x  its 64 k values. States read via __ldcg.
// ======================================================================
__global__ void __launch_bounds__(TPB_SCAN, 1)
k_scan(const float* __restrict__ Whh0, const float* __restrict__ Wih1,
       const float* __restrict__ Whh1,
       const float* __restrict__ bih1, const float* __restrict__ bhh1) {
    extern __shared__ float sm[];
    float2* wp0    = (float2*)sm;            // [1024][8] (w,w) pairs, 64 KB
    float2* wpA    = wp0 + 8192;             // Wih1
    float2* wpB    = wpA + 8192;             // Whh1
    float*  red    = (float*)(wpB + 8192);   // [8 warps][2 mats][8 h][64 b], 32 KB
    float*  bias2s = red + 8192;             // [8]

    const int g    = blockIdx.x;
    const int tid  = threadIdx.x;
    const int w    = tid >> 5;
    const int lane = tid & 31;
    const int bq   = lane >> 1;       // 0..15
    const int kl   = lane & 1;
    const int b4   = bq * 4;

    // Load + transpose + duplicate this block's weight rows (one-time).
    for (int idx = tid; idx < HB * HH; idx += TPB_SCAN) {
        int j = idx >> 10, kk = idx & 1023;
        float v0 = Whh0[(size_t)(g * HB + j) * HH + kk];
        float va = Wih1[(size_t)(g * HB + j) * HH + kk];
        float vb = Whh1[(size_t)(g * HB + j) * HH + kk];
        wp0[kk * 8 + j] = make_float2(v0, v0);
        wpA[kk * 8 + j] = make_float2(va, va);
        wpB[kk * 8 + j] = make_float2(vb, vb);
    }
    if (tid < HB) bias2s[tid] = bih1[g * HB + tid] + bhh1[g * HB + tid];
    __syncthreads();

    const int k0 = w * 128 + kl;      // thread's first k; step 2, 64 iters
    unsigned syncno = 0;

    for (int t = 0; t <= TT; t++) {
        const float* s1base = g_h1[(t + 1) & 1];   // h1[t-1]
        const float* s2base = g_h2[t & 1];         // h2[t-2]

        ull a1[16], a2[16];
#pragma unroll
        for (int i = 0; i < 16; i++) { a1[i] = 0ull; a2[i] = 0ull; }

        const float*  p1 = s1base + (size_t)k0 * BB + b4;
        const float*  p2 = s2base + (size_t)k0 * BB + b4;
        const float2* wr = wp0 + (size_t)k0 * 8;   // all three mats share k*8 offset

        F4U s1n, s2n;
        s1n.f = __ldcg((const float4*)p1);
        s2n.f = __ldcg((const float4*)p2);

#pragma unroll 2
        for (int i = 0; i < 64; i++) {
            F4U s1 = s1n, s2 = s2n;
            if (i < 63) {
                s1n.f = __ldcg((const float4*)(p1 + 128));
                s2n.f = __ldcg((const float4*)(p2 + 128));
            }
            p1 += 128; p2 += 128;

            const float4* W0 = (const float4*)(wr);
            const float4* WA = (const float4*)(wpA + (wr - wp0));
            const float4* WB = (const float4*)(wpB + (wr - wp0));
            F4U q0, q1, q2, q3;

            // h1 accum: Whh0 . h1[t-1]
            q0.f = W0[0]; q1.f = W0[1]; q2.f = W0[2]; q3.f = W0[3];
            FFMA2(a1[ 0], q0.u[0], s1.u[0]); FFMA2(a1[ 1], q0.u[0], s1.u[1]);
            FFMA2(a1[ 2], q0.u[1], s1.u[0]); FFMA2(a1[ 3], q0.u[1], s1.u[1]);
            FFMA2(a1[ 4], q1.u[0], s1.u[0]); FFMA2(a1[ 5], q1.u[0], s1.u[1]);
            FFMA2(a1[ 6], q1.u[1], s1.u[0]); FFMA2(a1[ 7], q1.u[1], s1.u[1]);
            FFMA2(a1[ 8], q2.u[0], s1.u[0]); FFMA2(a1[ 9], q2.u[0], s1.u[1]);
            FFMA2(a1[10], q2.u[1], s1.u[0]); FFMA2(a1[11], q2.u[1], s1.u[1]);
            FFMA2(a1[12], q3.u[0], s1.u[0]); FFMA2(a1[13], q3.u[0], s1.u[1]);
            FFMA2(a1[14], q3.u[1], s1.u[0]); FFMA2(a1[15], q3.u[1], s1.u[1]);

            // h2 accum part 1: Wih1 . h1[t-1]
            q0.f = WA[0]; q1.f = WA[1]; q2.f = WA[2]; q3.f = WA[3];
            FFMA2(a2[ 0], q0.u[0], s1.u[0]); FFMA2(a2[ 1], q0.u[0], s1.u[1]);
            FFMA2(a2[ 2], q0.u[1], s1.u[0]); FFMA2(a2[ 3], q0.u[1], s1.u[1]);
            FFMA2(a2[ 4], q1.u[0], s1.u[0]); FFMA2(a2[ 5], q1.u[0], s1.u[1]);
            FFMA2(a2[ 6], q1.u[1], s1.u[0]); FFMA2(a2[ 7], q1.u[1], s1.u[1]);
            FFMA2(a2[ 8], q2.u[0], s1.u[0]); FFMA2(a2[ 9], q2.u[0], s1.u[1]);
            FFMA2(a2[10], q2.u[1], s1.u[0]); FFMA2(a2[11], q2.u[1], s1.u[1]);
            FFMA2(a2[12], q3.u[0], s1.u[0]); FFMA2(a2[13], q3.u[0], s1.u[1]);
            FFMA2(a2[14], q3.u[1], s1.u[0]); FFMA2(a2[15], q3.u[1], s1.u[1]);

            // h2 accum part 2: Whh1 . h2[t-2]
            q0.f = WB[0]; q1.f = WB[1]; q2.f = WB[2]; q3.f = WB[3];
            FFMA2(a2[ 0], q0.u[0], s2.u[0]); FFMA2(a2[ 1], q0.u[0], s2.u[1]);
            FFMA2(a2[ 2], q0.u[1], s2.u[0]); FFMA2(a2[ 3], q0.u[1], s2.u[1]);
            FFMA2(a2[ 4], q1.u[0], s2.u[0]); FFMA2(a2[ 5], q1.u[0], s2.u[1]);
            FFMA2(a2[ 6], q1.u[1], s2.u[0]); FFMA2(a2[ 7], q1.u[1], s2.u[1]);
            FFMA2(a2[ 8], q2.u[0], s2.u[0]); FFMA2(a2[ 9], q2.u[0], s2.u[1]);
            FFMA2(a2[10], q2.u[1], s2.u[0]); FFMA2(a2[11], q2.u[1], s2.u[1]);
            FFMA2(a2[12], q3.u[0], s2.u[0]); FFMA2(a2[13], q3.u[0], s2.u[1]);
            FFMA2(a2[14], q3.u[1], s2.u[0]); FFMA2(a2[15], q3.u[1], s2.u[1]);

            wr += 16;
        }

        // Reduce across klane (adjacent lanes) with 64-bit shfl + packed add.
#pragma unroll
        for (int i = 0; i < 16; i++) {
            ull o1 = __shfl_xor_sync(0xffffffffu, a1[i], 1); FADD2(a1[i], o1);
            ull o2 = __shfl_xor_sync(0xffffffffu, a2[i], 1); FADD2(a2[i], o2);
        }

        // Warp partials -> SMEM (klane 0 lanes only).
        if (kl == 0) {
#pragma unroll
            for (int h = 0; h < 8; h++) {
                F4U o;
                o.u[0] = a1[h * 2]; o.u[1] = a1[h * 2 + 1];
                *(float4*)&red[((w * 2 + 0) * 8 + h) * 64 + b4] = o.f;
                o.u[0] = a2[h * 2]; o.u[1] = a2[h * 2 + 1];
                *(float4*)&red[((w * 2 + 1) * 8 + h) * 64 + b4] = o.f;
            }
        }
        __syncthreads();

        // Finale: 256 threads each own 4 output values (sum 8 warp partials,
        // add pre0/bias, tanh, store).
        {
            const int mat = tid >> 7;            // 0 = h1, 1 = h2
            const int hl  = (tid >> 4) & 7;
            const int b0  = (tid & 15) * 4;
            float4 s = make_float4(0.f, 0.f, 0.f, 0.f);
#pragma unroll
            for (int p = 0; p < 8; p++) {
                float4 v = *(const float4*)&red[((p * 16) + mat * 8 + hl) * 64 + b0];
                s.x += v.x; s.y += v.y; s.z += v.z; s.w += v.w;
            }
            if (mat == 0) {
                if (t < TT) {
                    float4 pre = __ldg((const float4*)&g_pre0[((size_t)t * HH + g * HB + hl) * BB + b0]);
                    s.x = tanhf(s.x + pre.x); s.y = tanhf(s.y + pre.y);
                    s.z = tanhf(s.z + pre.z); s.w = tanhf(s.w + pre.w);
                    __stcg((float4*)&g_h1[t & 1][(g * HB + hl) * BB + b0], s);
                }
            } else if (t > 0) {
                float bb = bias2s[hl];
                s.x = tanhf(s.x + bb); s.y = tanhf(s.y + bb);
                s.z = tanhf(s.z + bb); s.w = tanhf(s.w + bb);
                // h2[t-1] -> buffer (t-1)&1 == (t+1)&1
                __stcg((float4*)&g_h2[(t + 1) & 1][(g * HB + hl) * BB + b0], s);
            }
        }

        if (t < TT) gsync(++syncno);
    }
}

// ======================================================================
// Kernel 3: out[b] = sigmoid(h2[511][:,b] . W_fc + b_fc).  h2[511] is in buf 1.
// ======================================================================
__global__ void k_fc(const float* __restrict__ Wfc, const float* __restrict__ bfc,
                     float* __restrict__ out) {
    __shared__ float redm[256];
    const int tid = threadIdx.x;
    const int b = tid & 63, part = tid >> 6;
    float s = 0.f;
    for (int hh = part * 256; hh < part * 256 + 256; hh++)
        s += g_h2[1][hh * BB + b] * Wfc[hh];
    redm[tid] = s;
    __syncthreads();
    if (tid < 64) {
        float v = redm[tid] + redm[tid + 64] + redm[tid + 128] + redm[tid + 192] + bfc[0];
        out[b] = 1.f / (1.f + expf(-v));
    }
}

// ======================================================================
// Kernel 0: per-launch reset (determinism across graph replays).
// ======================================================================
__global__ void k_init() {
    int i = blockIdx.x * blockDim.x + threadIdx.x;
    if (i == 0) g_bar = 0u;
    if (i < HH * BB) {
        g_h1[0][i] = 0.f; g_h1[1][i] = 0.f;
        g_h2[0][i] = 0.f; g_h2[1][i] = 0.f;
    }
}

// ======================================================================
extern "C" void kernel_launch(void* const* d_in, const int* in_sizes, int n_in,
                              void* d_out, int out_size) {
    const int*   x    = (const int*)  d_in[0];
    const float* emb  = (const float*)d_in[1];
    const float* Wih0 = (const float*)d_in[2];
    const float* Whh0 = (const float*)d_in[3];
    const float* bih0 = (const float*)d_in[4];
    const float* bhh0 = (const float*)d_in[5];
    const float* Wih1 = (const float*)d_in[6];
    const float* Whh1 = (const float*)d_in[7];
    const float* bih1 = (const float*)d_in[8];
    const float* bhh1 = (const float*)d_in[9];
    const float* Wfc  = (const float*)d_in[10];
    const float* bfc  = (const float*)d_in[11];
    float* out = (float*)d_out;

    const int pre0_smem = 2 * EE * 65 * (int)sizeof(float);              // 156,000 B
    const int scan_smem = (3 * 8192) * 8 + 8192 * 4 + 64;                // 229,440 B
    cudaFuncSetAttribute(k_pre0, cudaFuncAttributeMaxDynamicSharedMemorySize, pre0_smem);
    cudaFuncSetAttribute(k_scan, cudaFuncAttributeMaxDynamicSharedMemorySize, scan_smem);

    k_init<<<(HH * BB + 255) / 256, 256>>>();
    k_pre0<<<dim3(HH / 64, TT), 256, pre0_smem>>>(x, emb, Wih0, bih0, bhh0);
    k_scan<<<GRID_SCAN, TPB_SCAN, scan_smem>>>(Whh0, Wih1, Whh1, bih1, bhh1);
    k_fc<<<1, 256>>>(Wfc, bfc, out);
}

// round 9
// speedup vs baseline: 2.3831x; 1.1537x over previous
#include <cuda_runtime.h>
#include <math.h>

// Problem constants
#define BB 64          // batch
#define TT 512         // time steps
#define HH 1024        // hidden
#define EE 300         // embedding dim

#define GRID_SCAN 128  // persistent blocks, 1 block/SM via SMEM => all co-resident
#define TPB_SCAN  256
#define HB 8           // h-rows owned per scan block (128*8 = 1024)

typedef unsigned long long ull;

// ---------------- device scratch (no allocations allowed) ----------------
__device__ __align__(256) float g_pre0[(size_t)TT * HH * BB]; // [t][h][b], 128 MB
__device__ __align__(256) float g_h1[2][HH * BB];             // ping-pong [h][b]
__device__ __align__(256) float g_h2[2][HH * BB];
__device__ unsigned             g_bar;

// ---------------- packed f32x2 helpers ----------------
#define FFMA2(d, a, b) asm("fma.rn.f32x2 %0, %1, %2, %0;" : "+l"(d) : "l"(a), "l"(b))
#define FADD2(d, a)    asm("add.rn.f32x2 %0, %0, %1;"     : "+l"(d) : "l"(a))

union F4U { float4 f; ull u[2]; };

// Monotone grid barrier: counter zeroed by k_init each launch.
__device__ __forceinline__ void gsync(unsigned n) {
    __threadfence();
    __syncthreads();
    if (threadIdx.x == 0) {
        atomicAdd(&g_bar, 1u);
        const unsigned tgt = n * GRID_SCAN;
        while (*((volatile unsigned*)&g_bar) < tgt) { }
    }
    __syncthreads();
}

// 16 packed FMAs: 8 h-rows (4 float4 of (w,w) pairs) x 4 b (2 packed pairs)
__device__ __forceinline__ void mat16(ull* acc, const float4* W, const ull* su) {
    F4U q0, q1, q2, q3;
    q0.f = W[0]; q1.f = W[1]; q2.f = W[2]; q3.f = W[3];
    FFMA2(acc[ 0], q0.u[0], su[0]); FFMA2(acc[ 1], q0.u[0], su[1]);
    FFMA2(acc[ 2], q0.u[1], su[0]); FFMA2(acc[ 3], q0.u[1], su[1]);
    FFMA2(acc[ 4], q1.u[0], su[0]); FFMA2(acc[ 5], q1.u[0], su[1]);
    FFMA2(acc[ 6], q1.u[1], su[0]); FFMA2(acc[ 7], q1.u[1], su[1]);
    FFMA2(acc[ 8], q2.u[0], su[0]); FFMA2(acc[ 9], q2.u[0], su[1]);
    FFMA2(acc[10], q2.u[1], su[0]); FFMA2(acc[11], q2.u[1], su[1]);
    FFMA2(acc[12], q3.u[0], su[0]); FFMA2(acc[13], q3.u[0], su[1]);
    FFMA2(acc[14], q3.u[1], su[0]); FFMA2(acc[15], q3.u[1], su[1]);
}

// ======================================================================
// Kernel 1: pre0[t][h][b] = sum_e emb[x[b][t]][e]*W_ih0[h][e] + b_ih0[h] + b_hh0[h]
// FFMA2 version: W pre-duplicated as (w,w) pairs in SMEM.
// ======================================================================
__global__ void k_pre0(const int* __restrict__ x, const float* __restrict__ emb,
                       const float* __restrict__ Wih0,
                       const float* __restrict__ bih0, const float* __restrict__ bhh0) {
    extern __shared__ float sm[];
    float*  As  = sm;                       // [300][64]  As[c*64 + b]
    float2* Ws2 = (float2*)(sm + EE * 64);  // [300][64]  (w,w) pairs, Ws2[c*64 + h]
    __shared__ int toks[64];

    const int tid   = threadIdx.x;
    const int t     = blockIdx.y;
    const int hbase = blockIdx.x * 64;

    if (tid < 64) toks[tid] = x[tid * TT + t];
    __syncthreads();

    for (int idx = tid; idx < 64 * EE; idx += 256) {
        int r = idx / EE, c = idx - r * EE;
        As[c * 64 + r] = emb[(size_t)toks[r] * EE + c];
        float wv = Wih0[(size_t)(hbase + r) * EE + c];
        Ws2[c * 64 + r] = make_float2(wv, wv);
    }
    __syncthreads();

    const int tx = tid & 15;    // b-quad
    const int ty = tid >> 4;    // h-quad
    ull acc2[4][2];
#pragma unroll
    for (int j = 0; j < 4; j++) { acc2[j][0] = 0ull; acc2[j][1] = 0ull; }

#pragma unroll 4
    for (int c = 0; c < EE; c++) {
        ull a01 = *(const ull*)(As + c * 64 + tx * 4);
        ull a23 = *(const ull*)(As + c * 64 + tx * 4 + 2);
        F4U w01, w23;
        w01.f = *(const float4*)(Ws2 + c * 64 + ty * 4);
        w23.f = *(const float4*)(Ws2 + c * 64 + ty * 4 + 2);
        FFMA2(acc2[0][0], w01.u[0], a01); FFMA2(acc2[0][1], w01.u[0], a23);
        FFMA2(acc2[1][0], w01.u[1], a01); FFMA2(acc2[1][1], w01.u[1], a23);
        FFMA2(acc2[2][0], w23.u[0], a01); FFMA2(acc2[2][1], w23.u[0], a23);
        FFMA2(acc2[3][0], w23.u[1], a01); FFMA2(acc2[3][1], w23.u[1], a23);
    }

#pragma unroll
    for (int j = 0; j < 4; j++) {
        int h = hbase + ty * 4 + j;
        float bs = bih0[h] + bhh0[h];
        F4U o; o.u[0] = acc2[j][0]; o.u[1] = acc2[j][1];
        float4 v = make_float4(o.f.x + bs, o.f.y + bs, o.f.z + bs, o.f.w + bs);
        *(float4*)(&g_pre0[((size_t)t * HH + h) * BB + tx * 4]) = v;
    }
}

// ======================================================================
// Kernel 2: persistent scan. Iter t computes h1[t] AND h2[t-1] (lagged),
// ONE grid barrier per iter. Deep software pipeline (ping-pong 4-iter
// register buffers, 8 LDG.128 batch-issued a phase ahead) hides L2 latency.
// ======================================================================
__global__ void __launch_bounds__(TPB_SCAN, 1)
k_scan(const float* __restrict__ Whh0, const float* __restrict__ Wih1,
       const float* __restrict__ Whh1,
       const float* __restrict__ bih1, const float* __restrict__ bhh1) {
    extern __shared__ float sm[];
    float2* wp0    = (float2*)sm;            // [1024][8] (w,w) pairs, 64 KB
    float2* wpA    = wp0 + 8192;             // Wih1
    float2* wpB    = wpA + 8192;             // Whh1
    float*  red    = (float*)(wpB + 8192);   // [8 warps][2 mats][8 h][64 b], 32 KB
    float*  bias2s = red + 8192;             // [8]

    const int g    = blockIdx.x;
    const int tid  = threadIdx.x;
    const int w    = tid >> 5;
    const int lane = tid & 31;
    const int bq   = lane >> 1;       // 0..15
    const int kl   = lane & 1;
    const int b4   = bq * 4;

    // Finale mapping (also used for pre0 prefetch)
    const int matf = tid >> 7;            // 0 = h1, 1 = h2
    const int hlf  = (tid >> 4) & 7;
    const int b0f  = (tid & 15) * 4;

    // Load + transpose + duplicate this block's weight rows (one-time).
    for (int idx = tid; idx < HB * HH; idx += TPB_SCAN) {
        int j = idx >> 10, kk = idx & 1023;
        float v0 = Whh0[(size_t)(g * HB + j) * HH + kk];
        float va = Wih1[(size_t)(g * HB + j) * HH + kk];
        float vb = Whh1[(size_t)(g * HB + j) * HH + kk];
        wp0[kk * 8 + j] = make_float2(v0, v0);
        wpA[kk * 8 + j] = make_float2(va, va);
        wpB[kk * 8 + j] = make_float2(vb, vb);
    }
    if (tid < HB) bias2s[tid] = bih1[g * HB + tid] + bhh1[g * HB + tid];
    __syncthreads();

    const int k0 = w * 128 + kl;      // thread's first k; step 2, 64 iters
    unsigned syncno = 0;

    for (int t = 0; t <= TT; t++) {
        const float* s1base = g_h1[(t + 1) & 1];   // h1[t-1]
        const float* s2base = g_h2[t & 1];         // h2[t-2]

        // Early prefetch of this step's pre0 operand for the finale.
        float4 pre_pref;
        if (matf == 0 && t < TT)
            pre_pref = __ldg((const float4*)&g_pre0[((size_t)t * HH + g * HB + hlf) * BB + b0f]);

        ull a1[16], a2[16];
#pragma unroll
        for (int i = 0; i < 16; i++) { a1[i] = 0ull; a2[i] = 0ull; }

        const float*  p1 = s1base + (size_t)k0 * BB + b4;
        const float*  p2 = s2base + (size_t)k0 * BB + b4;
        const float4* w0f4 = (const float4*)wp0 + (size_t)k0 * 4;
        const float4* wAf4 = (const float4*)wpA + (size_t)k0 * 4;
        const float4* wBf4 = (const float4*)wpB + (size_t)k0 * 4;

        F4U A1[4], A2[4], B1[4], B2[4];
#pragma unroll
        for (int j = 0; j < 4; j++) {                 // preload iters 0..3
            A1[j].f = __ldcg((const float4*)(p1 + (size_t)j * 128));
            A2[j].f = __ldcg((const float4*)(p2 + (size_t)j * 128));
        }

        auto do4 = [&](F4U* c1, F4U* c2, F4U* n1, F4U* n2, int base) {
            // batch-prefetch the NEXT 4 iters (distance 4..8 iters ahead)
#pragma unroll
            for (int j = 0; j < 4; j++) {
                int it = base + 4 + j;
                if (it < 64) {
                    n1[j].f = __ldcg((const float4*)(p1 + (size_t)it * 128));
                    n2[j].f = __ldcg((const float4*)(p2 + (size_t)it * 128));
                }
            }
            // consume current 4 iters
#pragma unroll
            for (int j = 0; j < 4; j++) {
                int i = base + j;
                mat16(a1, w0f4 + (size_t)i * 8, c1[j].u);
                mat16(a2, wAf4 + (size_t)i * 8, c1[j].u);
                mat16(a2, wBf4 + (size_t)i * 8, c2[j].u);
            }
        };

        for (int base = 0; base < 64; base += 8) {
            do4(A1, A2, B1, B2, base);
            do4(B1, B2, A1, A2, base + 4);
        }

        // Reduce across klane (adjacent lanes) with 64-bit shfl + packed add.
#pragma unroll
        for (int i = 0; i < 16; i++) {
            ull o1 = __shfl_xor_sync(0xffffffffu, a1[i], 1); FADD2(a1[i], o1);
            ull o2 = __shfl_xor_sync(0xffffffffu, a2[i], 1); FADD2(a2[i], o2);
        }

        // Warp partials -> SMEM (klane 0 lanes only).
        if (kl == 0) {
#pragma unroll
            for (int h = 0; h < 8; h++) {
                F4U o;
                o.u[0] = a1[h * 2]; o.u[1] = a1[h * 2 + 1];
                *(float4*)&red[((w * 2 + 0) * 8 + h) * 64 + b4] = o.f;
                o.u[0] = a2[h * 2]; o.u[1] = a2[h * 2 + 1];
                *(float4*)&red[((w * 2 + 1) * 8 + h) * 64 + b4] = o.f;
            }
        }
        __syncthreads();

        // Finale: 256 threads each own 4 output values.
        {
            float4 s = make_float4(0.f, 0.f, 0.f, 0.f);
#pragma unroll
            for (int p = 0; p < 8; p++) {
                float4 v = *(const float4*)&red[((p * 16) + matf * 8 + hlf) * 64 + b0f];
                s.x += v.x; s.y += v.y; s.z += v.z; s.w += v.w;
            }
            if (matf == 0) {
                if (t < TT) {
                    s.x = tanhf(s.x + pre_pref.x); s.y = tanhf(s.y + pre_pref.y);
                    s.z = tanhf(s.z + pre_pref.z); s.w = tanhf(s.w + pre_pref.w);
                    __stcg((float4*)&g_h1[t & 1][(g * HB + hlf) * BB + b0f], s);
                }
            } else if (t > 0) {
                float bb = bias2s[hlf];
                s.x = tanhf(s.x + bb); s.y = tanhf(s.y + bb);
                s.z = tanhf(s.z + bb); s.w = tanhf(s.w + bb);
                // h2[t-1] -> buffer (t-1)&1 == (t+1)&1
                __stcg((float4*)&g_h2[(t + 1) & 1][(g * HB + hlf) * BB + b0f], s);
            }
        }

        if (t < TT) gsync(++syncno);
    }
}

// ======================================================================
// Kernel 3: out[b] = sigmoid(h2[511][:,b] . W_fc + b_fc).  h2[511] is in buf 1.
// ======================================================================
__global__ void k_fc(const float* __restrict__ Wfc, const float* __restrict__ bfc,
                     float* __restrict__ out) {
    __shared__ float redm[256];
    const int tid = threadIdx.x;
    const int b = tid & 63, part = tid >> 6;
    float s = 0.f;
    for (int hh = part * 256; hh < part * 256 + 256; hh++)
        s += g_h2[1][hh * BB + b] * Wfc[hh];
    redm[tid] = s;
    __syncthreads();
    if (tid < 64) {
        float v = redm[tid] + redm[tid + 64] + redm[tid + 128] + redm[tid + 192] + bfc[0];
        out[b] = 1.f / (1.f + expf(-v));
    }
}

// ======================================================================
// Kernel 0: per-launch reset (determinism across graph replays).
// ======================================================================
__global__ void k_init() {
    int i = blockIdx.x * blockDim.x + threadIdx.x;
    if (i == 0) g_bar = 0u;
    if (i < HH * BB) {
        g_h1[0][i] = 0.f; g_h1[1][i] = 0.f;
        g_h2[0][i] = 0.f; g_h2[1][i] = 0.f;
    }
}

// ======================================================================
extern "C" void kernel_launch(void* const* d_in, const int* in_sizes, int n_in,
                              void* d_out, int out_size) {
    const int*   x    = (const int*)  d_in[0];
    const float* emb  = (const float*)d_in[1];
    const float* Wih0 = (const float*)d_in[2];
    const float* Whh0 = (const float*)d_in[3];
    const float* bih0 = (const float*)d_in[4];
    const float* bhh0 = (const float*)d_in[5];
    const float* Wih1 = (const float*)d_in[6];
    const float* Whh1 = (const float*)d_in[7];
    const float* bih1 = (const float*)d_in[8];
    const float* bhh1 = (const float*)d_in[9];
    const float* Wfc  = (const float*)d_in[10];
    const float* bfc  = (const float*)d_in[11];
    float* out = (float*)d_out;

    const int pre0_smem = (EE * 64) * 4 + (EE * 64) * 8;                 // 230,400 B
    const int scan_smem = (3 * 8192) * 8 + 8192 * 4 + 64;                // 229,440 B
    cudaFuncSetAttribute(k_pre0, cudaFuncAttributeMaxDynamicSharedMemorySize, pre0_smem);
    cudaFuncSetAttribute(k_scan, cudaFuncAttributeMaxDynamicSharedMemorySize, scan_smem);

    k_init<<<(HH * BB + 255) / 256, 256>>>();
    k_pre0<<<dim3(HH / 64, TT), 256, pre0_smem>>>(x, emb, Wih0, bih0, bhh0);
    k_scan<<<GRID_SCAN, TPB_SCAN, scan_smem>>>(Whh0, Wih1, Whh1, bih1, bhh1);
    k_fc<<<1, 256>>>(Wfc, bfc, out);
}